// round 13
// baseline (speedup 1.0000x reference)
#include <cuda_runtime.h>
#include <cuda_fp16.h>
#include <cstdint>

// ============================================================================
// MultiLoraLinear — fp16 HMMA path, v10 (explicit ldsm/mma interleave)
//   out = x @ W^T + bias + LoRA(per-segment, rank 16)
//
// CRITICAL RULE: NEVER pass a __device__ global as a kernel argument from
// host code (host-side shadow address; on GB300/ATS it silently writes host
// memory). All scratch globals are referenced from device code only.
//
// v10: asm-volatile ldsm/mma cannot be reordered by the compiler, so source
// order IS the schedule. The j-body is restructured from [6 ldsm; 16 mma]
// to [2 B-ldsm; A0-ldsm; mma0; A1-ldsm; mma1; ...] — first mma gated by 3
// loads instead of 6, remaining loads hidden under mma groups.
//
//   1) prep_kernel: sel + lora_A table + lora_B K-ext table (merged)
//   2) cvt_kernel : g_wh = half(W), g_xh = half(x) (merged)
//   3) xag_kernel : HMMA mini GEMM  g_xah = [x @ A_sel^T * scale | 0]
//   4) gemm_kernel: main GEMM, K = 65 chunks of 64 halves (last = LoRA ext)
// ============================================================================

#define DIN      4096
#define DOUT     4096
#define NBATCH   8
#define MROWS    16384
#define RANK     16
#define NLORA    3
#define SCALE_F  1.0f                // alpha / rank

#define BM       128
#define BN       128
#define BKH      64                  // K halves per chunk (= 128 B per row)
#define NCH      (DIN / BKH)         // 64 main chunks
#define NCHT     (NCH + 1)           // +1 LoRA extension chunk
#define GTHREADS 256

// GEMM SMEM (bytes): bias 128 floats | 3x A stage | 3x B stage
#define ROWB     144                 // padded row stride bytes (72 halves)
#define OFF_A    1024
#define A_STGB   (BM * ROWB)         // 18432
#define OFF_B    (OFF_A + 3 * A_STGB)
#define B_STGB   (BN * ROWB)         // 18432
#define SMEM_BYTES (OFF_B + 3 * B_STGB)   // 111616  -> 2 CTAs/SM

// merged prep kernel block ranges
#define BWHX_BLOCKS 4096             // (NLORA+1)*DOUT*64 / 256
#define LAH_BLOCKS  1024             // (NLORA+1)*RANK*DIN / 256
#define PREP_BLOCKS (BWHX_BLOCKS + LAH_BLOCKS + 1)

// merged convert kernel block ranges
#define WH_BLOCKS   8192             // DOUT*DIN/8/256
#define XH_BLOCKS   32768            // MROWS*DIN/8/256
#define CVT_BLOCKS  (WH_BLOCKS + XH_BLOCKS)

// ---------------------------------------------------------------------------
// device scratch (no cudaMalloc allowed; referenced ONLY from device code)
// ---------------------------------------------------------------------------
__device__ __half g_wh[(size_t)DOUT * DIN];                  // 32 MB
__device__ __half g_xh[(size_t)MROWS * DIN];                 // 128 MB
__device__ __half g_xah[(size_t)MROWS * BKH];                // 2 MB [xa|0]
__device__ __half g_bwhx[(size_t)(NLORA + 1) * DOUT * BKH];  // 2 MB
__device__ __half g_lahx[(size_t)(NLORA + 1) * RANK * DIN];  // 512 KB
__device__ int    g_sel[NBATCH];

// ---------------------------------------------------------------------------
// helpers
// ---------------------------------------------------------------------------
__device__ __forceinline__ uint32_t smem_u32(const void* p) {
    uint32_t a;
    asm("{ .reg .u64 t; cvta.to.shared.u64 t, %1; cvt.u32.u64 %0, t; }"
        : "=r"(a) : "l"(p));
    return a;
}

__device__ __forceinline__ void cp_async16(uint32_t dst_smem, const void* src) {
    asm volatile("cp.async.cg.shared.global [%0], [%1], 16;"
                 :: "r"(dst_smem), "l"(src) : "memory");
}
#define CP_COMMIT() asm volatile("cp.async.commit_group;" ::: "memory")
#define CP_WAIT1()  asm volatile("cp.async.wait_group 1;" ::: "memory")
#define CP_WAIT0()  asm volatile("cp.async.wait_group 0;" ::: "memory")

__device__ __forceinline__ void mma_f16(float* d, uint32_t a0, uint32_t a1,
                                        uint32_t a2, uint32_t a3,
                                        uint32_t b0, uint32_t b1) {
    asm volatile(
        "mma.sync.aligned.m16n8k16.row.col.f32.f16.f16.f32 "
        "{%0,%1,%2,%3}, {%4,%5,%6,%7}, {%8,%9}, {%0,%1,%2,%3};"
        : "+f"(d[0]), "+f"(d[1]), "+f"(d[2]), "+f"(d[3])
        : "r"(a0), "r"(a1), "r"(a2), "r"(a3), "r"(b0), "r"(b1));
}

__device__ __forceinline__ void ldsm4(uint32_t& r0, uint32_t& r1,
                                      uint32_t& r2, uint32_t& r3,
                                      uint32_t addr) {
    asm volatile("ldmatrix.sync.aligned.m8n8.x4.shared.b16 {%0,%1,%2,%3}, [%4];"
                 : "=r"(r0), "=r"(r1), "=r"(r2), "=r"(r3) : "r"(addr));
}

// ---------------------------------------------------------------------------
// 1) prep: sel + lora_A fp16 table + lora_B K-ext table, merged by blockIdx.
// ---------------------------------------------------------------------------
__global__ void __launch_bounds__(256) prep_kernel(
    const void* __restrict__ starts_raw, int n_starts,
    const float* __restrict__ lA, const float* __restrict__ lB) {
    const int bid = blockIdx.x;
    const int tid = threadIdx.x;

    if (bid < BWHX_BLOCKS) {
        // g_bwhx[a][n][c] = (a>0 && c<16) ? half(lora_B[a-1][n][c]) : 0
        int idx = bid * 256 + tid;
        int c = idx & 63;
        int n = (idx >> 6) & (DOUT - 1);
        int a = idx >> 18;
        float v = 0.0f;
        if (a > 0 && c < RANK)
            v = lB[((size_t)(a - 1) * DOUT + n) * RANK + c];
        g_bwhx[idx] = __float2half_rn(v);
    } else if (bid < BWHX_BLOCKS + LAH_BLOCKS) {
        // g_lahx: [0 | lora_A] fp16, slab 0 = zeros
        int idx = (bid - BWHX_BLOCKS) * 256 + tid;
        int a = idx >> 16;                       // / (RANK*DIN)
        float v = 0.0f;
        if (a > 0) v = lA[(size_t)idx - (size_t)RANK * DIN];
        g_lahx[idx] = __float2half_rn(v);
    } else if (tid < 32) {
        // sel: searchsorted(starts, b, 'right') - 1; dtype-robust (i32/i64)
        const long long* s64 = (const long long*)starts_raw;
        const int*       s32 = (const int*)starts_raw;
        bool ok64 = true;
        long long prev = -1;
        for (int j = 0; j < n_starts; j++) {
            long long v = s64[j];
            if (v < 0 || v >= 64 || v < prev) { ok64 = false; break; }
            prev = v;
        }
        int b = tid;
        if (b < NBATCH) {
            int cnt = 0;
            for (int j = 0; j < n_starts; j++) {
                long long v = ok64 ? s64[j] : (long long)s32[j];
                cnt += (v <= (long long)b);
            }
            int seg = cnt - 1;
            int id = 0;
            if (seg > 0) { id = seg; if (id > NLORA) id = NLORA; }
            g_sel[b] = id;
        }
    }
}

// ---------------------------------------------------------------------------
// 2) cvt: g_wh = half(W), g_xh = half(x), merged (8 floats / thread)
// ---------------------------------------------------------------------------
__device__ __forceinline__ void cvt8(const float4* s4, __half* dst, size_t idx) {
    float4 a = s4[2 * idx], b = s4[2 * idx + 1];
    __half2 h[4];
    h[0] = __floats2half2_rn(a.x, a.y);
    h[1] = __floats2half2_rn(a.z, a.w);
    h[2] = __floats2half2_rn(b.x, b.y);
    h[3] = __floats2half2_rn(b.z, b.w);
    *(uint4*)(dst + idx * 8) = *(const uint4*)h;
}

__global__ void __launch_bounds__(256) cvt_kernel(const float* __restrict__ W,
                                                  const float* __restrict__ x) {
    const int bid = blockIdx.x;
    if (bid < WH_BLOCKS) {
        size_t idx = (size_t)bid * 256 + threadIdx.x;
        cvt8((const float4*)W, g_wh, idx);
    } else {
        size_t idx = (size_t)(bid - WH_BLOCKS) * 256 + threadIdx.x;
        cvt8((const float4*)x, g_xh, idx);
    }
}

// ---------------------------------------------------------------------------
// 3) xag: g_xah[m][0:16] = scale * (g_xh[m] @ A_sel^T);  cols 16..63 = 0
//    128 rows / CTA, 8 warps (16 rows each), HMMA m16n8k16,
//    LDS.32 fragment loads, 2-stage cp.async.  (proven)
// ---------------------------------------------------------------------------
#define XR 144                       // padded row bytes
#define XS_STG (128 * XR)            // 18432
#define AS_STG (16 * XR)             // 2304

__global__ void __launch_bounds__(256) xag_kernel() {
    __shared__ char sm2[2 * XS_STG + 2 * AS_STG];   // 41472 B static
    const int tid  = threadIdx.x;
    const int lane = tid & 31;
    const int wid  = tid >> 5;
    const int gid  = lane >> 2;      // 0..7
    const int tig  = lane & 3;       // 0..3
    const int m0   = blockIdx.x * 128;
    const int sel  = g_sel[m0 >> 11];

    const int rowA = tid >> 3;       // 0..31 (+32*i)
    const int q    = tid & 7;
    const uint32_t sbase = smem_u32(sm2);
    const __half* srcX = g_xh + (size_t)(m0 + rowA) * DIN + q * 8;
    const __half* srcL = g_lahx + (size_t)sel * RANK * DIN
                       + (size_t)(tid >> 3) * DIN + q * 8;
    const uint32_t dstX = sbase + (uint32_t)(rowA * XR + q * 16);
    const uint32_t dstL = sbase + 2 * XS_STG + (uint32_t)((tid >> 3) * XR + q * 16);

#define XPF(cn, st) do {                                                      \
    const __half* _x = srcX + (size_t)(cn) * BKH;                             \
    _Pragma("unroll")                                                         \
    for (int i = 0; i < 4; i++)                                               \
        cp_async16(dstX + (st) * XS_STG + i * (32 * XR),                      \
                   _x + (size_t)(32 * i) * DIN);                              \
    if (tid < 128)                                                            \
        cp_async16(dstL + (st) * AS_STG, srcL + (size_t)(cn) * BKH);          \
} while (0)

    XPF(0, 0); CP_COMMIT();

    float d[2][4];
#pragma unroll
    for (int nt = 0; nt < 2; nt++)
#pragma unroll
        for (int r = 0; r < 4; r++) d[nt][r] = 0.0f;

    for (int c = 0; c < NCH; c++) {
        const int st = c & 1;
        CP_WAIT0();
        __syncthreads();
        if (c + 1 < NCH) { XPF(c + 1, st ^ 1); CP_COMMIT(); }

        const char* Xs = sm2 + st * XS_STG;
        const char* As = sm2 + 2 * XS_STG + st * AS_STG;
#pragma unroll
        for (int kk = 0; kk < 4; kk++) {
            const int koff = kk * 32;           // bytes (16 halves)
            const int r = wid * 16 + gid;
            const char* p0 = Xs + r * XR + koff + tig * 4;
            const char* p1 = Xs + (r + 8) * XR + koff + tig * 4;
            uint32_t a0 = *(const uint32_t*)(p0);
            uint32_t a1 = *(const uint32_t*)(p1);
            uint32_t a2 = *(const uint32_t*)(p0 + 16);
            uint32_t a3 = *(const uint32_t*)(p1 + 16);
            uint32_t b[2][2];
#pragma unroll
            for (int nt = 0; nt < 2; nt++) {
                const char* p = As + (nt * 8 + gid) * XR + koff + tig * 4;
                b[nt][0] = *(const uint32_t*)(p);
                b[nt][1] = *(const uint32_t*)(p + 16);
            }
            mma_f16(d[0], a0, a1, a2, a3, b[0][0], b[0][1]);
            mma_f16(d[1], a0, a1, a2, a3, b[1][0], b[1][1]);
        }
        __syncthreads();              // stage reuse guard before next overwrite
    }

    // epilogue: cols 0..15 from accumulators (std mma d layout), 16..63 zero
#pragma unroll
    for (int nt = 0; nt < 2; nt++) {
        const int col = nt * 8 + tig * 2;
        const int r0 = m0 + wid * 16 + gid;
        __half2 v0 = __floats2half2_rn(d[nt][0] * SCALE_F, d[nt][1] * SCALE_F);
        __half2 v1 = __floats2half2_rn(d[nt][2] * SCALE_F, d[nt][3] * SCALE_F);
        *(__half2*)(g_xah + (size_t)r0 * BKH + col) = v0;
        *(__half2*)(g_xah + (size_t)(r0 + 8) * BKH + col) = v1;
    }
    const uint4 z = {0u, 0u, 0u, 0u};
#pragma unroll
    for (int i = 0; i < 3; i++) {
        int idx = tid + i * 256;               // < 768 = 128 rows * 6 slots
        int row = idx / 6, slot = idx % 6;
        *(uint4*)(g_xah + (size_t)(m0 + row) * BKH + 16 + slot * 8) = z;
    }
#undef XPF
}

// ---------------------------------------------------------------------------
// 4) GEMM: out[m,n] = sum_{65 chunks} A.B + bias[n]
//    128x128 tiles, 8 warps of 64x32 (2x4 grid), 2 CTAs/SM, 3-stage
//    pipeline, ldmatrix.x4 loads, per-warp kk rotation, interleaved
//    ldsm/mma schedule, prefetch after the first mma group.
// ---------------------------------------------------------------------------
__global__ void __launch_bounds__(GTHREADS, 2)
gemm_kernel(const float* __restrict__ bias, float* __restrict__ out) {
    extern __shared__ char smem[];
    float* smf = (float*)smem;
    const int tid  = threadIdx.x;
    const int lane = tid & 31;
    const int wid  = tid >> 5;
    const int gid  = lane >> 2;      // 0..7
    const int tig  = lane & 3;       // 0..3
    const int wm   = wid & 1;        // warp M (2)
    const int wn   = wid >> 1;       // warp N (4)

    const int n0 = blockIdx.x * BN;
    const int m0 = blockIdx.y * BM;
    const int sel = g_sel[m0 >> 11];

    if (tid < BN) smf[tid] = bias[n0 + tid];

    const uint32_t sbase = smem_u32(smem);
    const int rowA = tid >> 3;       // 0..31 (+32*i)
    const int q    = tid & 7;        // 16B slot within 128B row
    const __half* srcA  = g_xh + (size_t)(m0 + rowA) * DIN + q * 8;
    const __half* srcB  = g_wh + (size_t)(n0 + rowA) * DIN + q * 8;
    const uint32_t dstA = sbase + OFF_A + (uint32_t)(rowA * ROWB + q * 16);
    const uint32_t dstB = sbase + OFF_B + (uint32_t)(rowA * ROWB + q * 16);

    // per-lane ldmatrix base offsets (R9-proven maps)
    const uint32_t aoffl = (uint32_t)((wm * 64 + (lane & 15)) * ROWB
                                      + ((lane >> 4) & 1) * 16);
    const uint32_t boffl = (uint32_t)((wn * 32 + ((lane >> 4) & 1) * 8
                                       + (lane & 7)) * ROWB
                                      + ((lane >> 3) & 1) * 16);

    // LoRA-ext sources rematerialized in the tail branch (keeps them out of
    // the mainloop's live register set)
#define PREFETCH(cn, st) do {                                                 \
    if ((cn) < NCH) {                                                         \
        const __half* _a = srcA + (size_t)(cn) * BKH;                         \
        const __half* _b = srcB + (size_t)(cn) * BKH;                         \
        _Pragma("unroll")                                                     \
        for (int i = 0; i < 4; i++)                                           \
            cp_async16(dstA + (st) * A_STGB + i * (32 * ROWB),                \
                       _a + (size_t)(32 * i) * DIN);                          \
        _Pragma("unroll")                                                     \
        for (int i = 0; i < 4; i++)                                           \
            cp_async16(dstB + (st) * B_STGB + i * (32 * ROWB),                \
                       _b + (size_t)(32 * i) * DIN);                          \
    } else {                                                                  \
        const __half* _ae = g_xah  + (size_t)(m0 + rowA) * BKH + q * 8;       \
        const __half* _be = g_bwhx + ((size_t)sel * DOUT + (n0 + rowA)) * BKH \
                          + q * 8;                                            \
        _Pragma("unroll")                                                     \
        for (int i = 0; i < 4; i++)                                           \
            cp_async16(dstA + (st) * A_STGB + i * (32 * ROWB),                \
                       _ae + (size_t)(32 * i) * BKH);                         \
        _Pragma("unroll")                                                     \
        for (int i = 0; i < 4; i++)                                           \
            cp_async16(dstB + (st) * B_STGB + i * (32 * ROWB),                \
                       _be + (size_t)(32 * i) * BKH);                         \
    }                                                                         \
} while (0)

    PREFETCH(0, 0); CP_COMMIT();
    PREFETCH(1, 1); CP_COMMIT();

    // per-warp kk rotation: all 4 phases present on each SMSP (wid 0..7)
    const uint32_t kbase = (uint32_t)(wid & 3) * 32u;

    float d[4][4][4];
#pragma unroll
    for (int mt = 0; mt < 4; mt++)
#pragma unroll
        for (int nt = 0; nt < 4; nt++)
#pragma unroll
            for (int r = 0; r < 4; r++) d[mt][nt][r] = 0.0f;

    for (int c = 0; c < NCHT; c++) {
        const int st = c % 3;
        CP_WAIT1();                   // chunk c's group complete
        __syncthreads();              // all warps done with stage (c-1)%3

        const uint32_t As = sbase + OFF_A + st * A_STGB + aoffl;
        const uint32_t Bs = sbase + OFF_B + st * B_STGB + boffl;

#pragma unroll
        for (int j = 0; j < 4; j++) {
            const uint32_t koff = (kbase + (uint32_t)j * 32u) & 127u;

            // ---- interleaved schedule: B, A0, mma0, A1, mma1, ... ----
            uint32_t b[4][2];
            ldsm4(b[0][0], b[0][1], b[1][0], b[1][1], Bs + koff);
            ldsm4(b[2][0], b[2][1], b[3][0], b[3][1], Bs + 16 * ROWB + koff);

            uint32_t a[4][4];
            ldsm4(a[0][0], a[0][1], a[0][2], a[0][3], As + koff);
#pragma unroll
            for (int mt = 0; mt < 4; mt++) {
                if (mt < 3)
                    ldsm4(a[mt + 1][0], a[mt + 1][1], a[mt + 1][2], a[mt + 1][3],
                          As + (mt + 1) * (16 * ROWB) + koff);
#pragma unroll
                for (int nt = 0; nt < 4; nt++)
                    mma_f16(d[mt][nt], a[mt][0], a[mt][1], a[mt][2], a[mt][3],
                            b[nt][0], b[nt][1]);
            }

            // issue next-next chunk's prefetch after the first j block
            if (j == 0) {
                int cn = c + 2; if (cn > NCH) cn = NCH;   // clamped tail
                PREFETCH(cn, (c + 2) % 3);
                CP_COMMIT();
            }
        }
    }
    CP_WAIT0();

    // ---- epilogue: fused bias ----
    const float* bs = smf + wn * 32;
#pragma unroll
    for (int mt = 0; mt < 4; mt++) {
        const int r = m0 + wm * 64 + mt * 16 + gid;
        float* o0p = out + (size_t)r * DOUT + n0 + wn * 32;
        float* o1p = o0p + (size_t)8 * DOUT;
#pragma unroll
        for (int nt = 0; nt < 4; nt++) {
            const int col = nt * 8 + tig * 2;
            float2 v0, v1;
            v0.x = d[mt][nt][0] + bs[col];
            v0.y = d[mt][nt][1] + bs[col + 1];
            v1.x = d[mt][nt][2] + bs[col];
            v1.y = d[mt][nt][3] + bs[col + 1];
            *(float2*)(o0p + col) = v0;
            *(float2*)(o1p + col) = v1;
        }
    }
#undef PREFETCH
}

// ---------------------------------------------------------------------------
// launch — gemm is launch index 3 (the slot ncu captures)
// ---------------------------------------------------------------------------
extern "C" void kernel_launch(void* const* d_in, const int* in_sizes, int n_in,
                              void* d_out, int out_size) {
    const float* x      = (const float*)d_in[0];
    const float* weight = (const float*)d_in[1];
    const float* bias   = (const float*)d_in[2];
    const float* lora_A = (const float*)d_in[3];
    const float* lora_B = (const float*)d_in[4];
    const void*  starts = d_in[5];
    float* out = (float*)d_out;
    const int n_starts = in_sizes[5];

    prep_kernel<<<PREP_BLOCKS, 256>>>(starts, n_starts, lora_A, lora_B);
    cvt_kernel<<<CVT_BLOCKS, 256>>>(weight, x);
    xag_kernel<<<MROWS / 128, 256>>>();

    cudaFuncSetAttribute(gemm_kernel,
                         cudaFuncAttributeMaxDynamicSharedMemorySize, SMEM_BYTES);
    dim3 grid(DOUT / BN, MROWS / BM);  // (32, 128)
    gemm_kernel<<<grid, GTHREADS, SMEM_BYTES>>>(bias, out);
}

// round 14
// speedup vs baseline: 1.0583x; 1.0583x over previous
#include <cuda_runtime.h>
#include <cuda_fp16.h>
#include <cstdint>

// ============================================================================
// MultiLoraLinear — fp16 HMMA path, v11 (R12 GEMM banked + consolidation)
//   out = x @ W^T + bias + LoRA(per-segment, rank 16)
//
// CRITICAL RULE: NEVER pass a __device__ global as a kernel argument from
// host code (host-side shadow address; on GB300/ATS it silently writes host
// memory). All scratch globals are referenced from device code only.
//
// v11: GEMM restored to the R12 configuration (best measured: 1421 us,
// tensor 71.6%) — 128x128 CTA, 8 warps of 64x32, 2 CTAs/SM, 3-stage
// cp.async, batched [6 ldsm; 16 mma] j-body with per-warp kk rotation.
// Only delta: the chunk prefetch is split A@j==0 / B@j==1 (one commit per
// chunk, unchanged accounting) to smooth the LSU burst. Prep merged into
// the convert kernel (one fewer launch).
//
//   1) cvt_kernel : g_wh = half(W), g_xh = half(x), + sel/lahx/bwhx tables
//   2) xag_kernel : HMMA mini GEMM  g_xah = [x @ A_sel^T * scale | 0]
//   3) gemm_kernel: main GEMM, K = 65 chunks of 64 halves (last = LoRA ext)
// ============================================================================

#define DIN      4096
#define DOUT     4096
#define NBATCH   8
#define MROWS    16384
#define RANK     16
#define NLORA    3
#define SCALE_F  1.0f                // alpha / rank

#define BM       128
#define BN       128
#define BKH      64                  // K halves per chunk (= 128 B per row)
#define NCH      (DIN / BKH)         // 64 main chunks
#define NCHT     (NCH + 1)           // +1 LoRA extension chunk
#define GTHREADS 256

// GEMM SMEM (bytes): bias 128 floats | 3x A stage | 3x B stage
#define ROWB     144                 // padded row stride bytes (72 halves)
#define OFF_A    1024
#define A_STGB   (BM * ROWB)         // 18432
#define OFF_B    (OFF_A + 3 * A_STGB)
#define B_STGB   (BN * ROWB)         // 18432
#define SMEM_BYTES (OFF_B + 3 * B_STGB)   // 111616  -> 2 CTAs/SM

// merged convert+prep kernel block ranges
#define WH_BLOCKS   8192             // DOUT*DIN/8/256
#define XH_BLOCKS   32768            // MROWS*DIN/8/256
#define BWHX_BLOCKS 4096             // (NLORA+1)*DOUT*64 / 256
#define LAH_BLOCKS  1024             // (NLORA+1)*RANK*DIN / 256
#define CVT_BLOCKS  (WH_BLOCKS + XH_BLOCKS + BWHX_BLOCKS + LAH_BLOCKS + 1)

// ---------------------------------------------------------------------------
// device scratch (no cudaMalloc allowed; referenced ONLY from device code)
// ---------------------------------------------------------------------------
__device__ __half g_wh[(size_t)DOUT * DIN];                  // 32 MB
__device__ __half g_xh[(size_t)MROWS * DIN];                 // 128 MB
__device__ __half g_xah[(size_t)MROWS * BKH];                // 2 MB [xa|0]
__device__ __half g_bwhx[(size_t)(NLORA + 1) * DOUT * BKH];  // 2 MB
__device__ __half g_lahx[(size_t)(NLORA + 1) * RANK * DIN];  // 512 KB
__device__ int    g_sel[NBATCH];

// ---------------------------------------------------------------------------
// helpers
// ---------------------------------------------------------------------------
__device__ __forceinline__ uint32_t smem_u32(const void* p) {
    uint32_t a;
    asm("{ .reg .u64 t; cvta.to.shared.u64 t, %1; cvt.u32.u64 %0, t; }"
        : "=r"(a) : "l"(p));
    return a;
}

__device__ __forceinline__ void cp_async16(uint32_t dst_smem, const void* src) {
    asm volatile("cp.async.cg.shared.global [%0], [%1], 16;"
                 :: "r"(dst_smem), "l"(src) : "memory");
}
#define CP_COMMIT() asm volatile("cp.async.commit_group;" ::: "memory")
#define CP_WAIT1()  asm volatile("cp.async.wait_group 1;" ::: "memory")
#define CP_WAIT0()  asm volatile("cp.async.wait_group 0;" ::: "memory")

__device__ __forceinline__ void mma_f16(float* d, uint32_t a0, uint32_t a1,
                                        uint32_t a2, uint32_t a3,
                                        uint32_t b0, uint32_t b1) {
    asm volatile(
        "mma.sync.aligned.m16n8k16.row.col.f32.f16.f16.f32 "
        "{%0,%1,%2,%3}, {%4,%5,%6,%7}, {%8,%9}, {%0,%1,%2,%3};"
        : "+f"(d[0]), "+f"(d[1]), "+f"(d[2]), "+f"(d[3])
        : "r"(a0), "r"(a1), "r"(a2), "r"(a3), "r"(b0), "r"(b1));
}

__device__ __forceinline__ void ldsm4(uint32_t& r0, uint32_t& r1,
                                      uint32_t& r2, uint32_t& r3,
                                      uint32_t addr) {
    asm volatile("ldmatrix.sync.aligned.m8n8.x4.shared.b16 {%0,%1,%2,%3}, [%4];"
                 : "=r"(r0), "=r"(r1), "=r"(r2), "=r"(r3) : "r"(addr));
}

__device__ __forceinline__ void cvt8(const float4* s4, __half* dst, size_t idx) {
    float4 a = s4[2 * idx], b = s4[2 * idx + 1];
    __half2 h[4];
    h[0] = __floats2half2_rn(a.x, a.y);
    h[1] = __floats2half2_rn(a.z, a.w);
    h[2] = __floats2half2_rn(b.x, b.y);
    h[3] = __floats2half2_rn(b.z, b.w);
    *(uint4*)(dst + idx * 8) = *(const uint4*)h;
}

// ---------------------------------------------------------------------------
// 1) cvt+prep merged: W->half, x->half, lora tables, sel — by blockIdx range
// ---------------------------------------------------------------------------
__global__ void __launch_bounds__(256) cvt_kernel(
    const float* __restrict__ W, const float* __restrict__ x,
    const float* __restrict__ lA, const float* __restrict__ lB,
    const void* __restrict__ starts_raw, int n_starts) {
    const int bid = blockIdx.x;
    const int tid = threadIdx.x;

    if (bid < WH_BLOCKS) {
        size_t idx = (size_t)bid * 256 + tid;
        cvt8((const float4*)W, g_wh, idx);
    } else if (bid < WH_BLOCKS + XH_BLOCKS) {
        size_t idx = (size_t)(bid - WH_BLOCKS) * 256 + tid;
        cvt8((const float4*)x, g_xh, idx);
    } else if (bid < WH_BLOCKS + XH_BLOCKS + BWHX_BLOCKS) {
        // g_bwhx[a][n][c] = (a>0 && c<16) ? half(lora_B[a-1][n][c]) : 0
        int idx = (bid - WH_BLOCKS - XH_BLOCKS) * 256 + tid;
        int c = idx & 63;
        int n = (idx >> 6) & (DOUT - 1);
        int a = idx >> 18;
        float v = 0.0f;
        if (a > 0 && c < RANK)
            v = lB[((size_t)(a - 1) * DOUT + n) * RANK + c];
        g_bwhx[idx] = __float2half_rn(v);
    } else if (bid < WH_BLOCKS + XH_BLOCKS + BWHX_BLOCKS + LAH_BLOCKS) {
        // g_lahx: [0 | lora_A] fp16, slab 0 = zeros
        int idx = (bid - WH_BLOCKS - XH_BLOCKS - BWHX_BLOCKS) * 256 + tid;
        int a = idx >> 16;                       // / (RANK*DIN)
        float v = 0.0f;
        if (a > 0) v = lA[(size_t)idx - (size_t)RANK * DIN];
        g_lahx[idx] = __float2half_rn(v);
    } else if (tid < 32) {
        // sel: searchsorted(starts, b, 'right') - 1; dtype-robust (i32/i64)
        const long long* s64 = (const long long*)starts_raw;
        const int*       s32 = (const int*)starts_raw;
        bool ok64 = true;
        long long prev = -1;
        for (int j = 0; j < n_starts; j++) {
            long long v = s64[j];
            if (v < 0 || v >= 64 || v < prev) { ok64 = false; break; }
            prev = v;
        }
        int b = tid;
        if (b < NBATCH) {
            int cnt = 0;
            for (int j = 0; j < n_starts; j++) {
                long long v = ok64 ? s64[j] : (long long)s32[j];
                cnt += (v <= (long long)b);
            }
            int seg = cnt - 1;
            int id = 0;
            if (seg > 0) { id = seg; if (id > NLORA) id = NLORA; }
            g_sel[b] = id;
        }
    }
}

// ---------------------------------------------------------------------------
// 2) xag: g_xah[m][0:16] = scale * (g_xh[m] @ A_sel^T);  cols 16..63 = 0
//    128 rows / CTA, 8 warps (16 rows each), HMMA m16n8k16,
//    LDS.32 fragment loads, 2-stage cp.async.  (proven)
// ---------------------------------------------------------------------------
#define XR 144                       // padded row bytes
#define XS_STG (128 * XR)            // 18432
#define AS_STG (16 * XR)             // 2304

__global__ void __launch_bounds__(256) xag_kernel() {
    __shared__ char sm2[2 * XS_STG + 2 * AS_STG];   // 41472 B static
    const int tid  = threadIdx.x;
    const int lane = tid & 31;
    const int wid  = tid >> 5;
    const int gid  = lane >> 2;      // 0..7
    const int tig  = lane & 3;       // 0..3
    const int m0   = blockIdx.x * 128;
    const int sel  = g_sel[m0 >> 11];

    const int rowA = tid >> 3;       // 0..31 (+32*i)
    const int q    = tid & 7;
    const uint32_t sbase = smem_u32(sm2);
    const __half* srcX = g_xh + (size_t)(m0 + rowA) * DIN + q * 8;
    const __half* srcL = g_lahx + (size_t)sel * RANK * DIN
                       + (size_t)(tid >> 3) * DIN + q * 8;
    const uint32_t dstX = sbase + (uint32_t)(rowA * XR + q * 16);
    const uint32_t dstL = sbase + 2 * XS_STG + (uint32_t)((tid >> 3) * XR + q * 16);

#define XPF(cn, st) do {                                                      \
    const __half* _x = srcX + (size_t)(cn) * BKH;                             \
    _Pragma("unroll")                                                         \
    for (int i = 0; i < 4; i++)                                               \
        cp_async16(dstX + (st) * XS_STG + i * (32 * XR),                      \
                   _x + (size_t)(32 * i) * DIN);                              \
    if (tid < 128)                                                            \
        cp_async16(dstL + (st) * AS_STG, srcL + (size_t)(cn) * BKH);          \
} while (0)

    XPF(0, 0); CP_COMMIT();

    float d[2][4];
#pragma unroll
    for (int nt = 0; nt < 2; nt++)
#pragma unroll
        for (int r = 0; r < 4; r++) d[nt][r] = 0.0f;

    for (int c = 0; c < NCH; c++) {
        const int st = c & 1;
        CP_WAIT0();
        __syncthreads();
        if (c + 1 < NCH) { XPF(c + 1, st ^ 1); CP_COMMIT(); }

        const char* Xs = sm2 + st * XS_STG;
        const char* As = sm2 + 2 * XS_STG + st * AS_STG;
#pragma unroll
        for (int kk = 0; kk < 4; kk++) {
            const int koff = kk * 32;           // bytes (16 halves)
            const int r = wid * 16 + gid;
            const char* p0 = Xs + r * XR + koff + tig * 4;
            const char* p1 = Xs + (r + 8) * XR + koff + tig * 4;
            uint32_t a0 = *(const uint32_t*)(p0);
            uint32_t a1 = *(const uint32_t*)(p1);
            uint32_t a2 = *(const uint32_t*)(p0 + 16);
            uint32_t a3 = *(const uint32_t*)(p1 + 16);
            uint32_t b[2][2];
#pragma unroll
            for (int nt = 0; nt < 2; nt++) {
                const char* p = As + (nt * 8 + gid) * XR + koff + tig * 4;
                b[nt][0] = *(const uint32_t*)(p);
                b[nt][1] = *(const uint32_t*)(p + 16);
            }
            mma_f16(d[0], a0, a1, a2, a3, b[0][0], b[0][1]);
            mma_f16(d[1], a0, a1, a2, a3, b[1][0], b[1][1]);
        }
        __syncthreads();              // stage reuse guard before next overwrite
    }

    // epilogue: cols 0..15 from accumulators (std mma d layout), 16..63 zero
#pragma unroll
    for (int nt = 0; nt < 2; nt++) {
        const int col = nt * 8 + tig * 2;
        const int r0 = m0 + wid * 16 + gid;
        __half2 v0 = __floats2half2_rn(d[nt][0] * SCALE_F, d[nt][1] * SCALE_F);
        __half2 v1 = __floats2half2_rn(d[nt][2] * SCALE_F, d[nt][3] * SCALE_F);
        *(__half2*)(g_xah + (size_t)r0 * BKH + col) = v0;
        *(__half2*)(g_xah + (size_t)(r0 + 8) * BKH + col) = v1;
    }
    const uint4 z = {0u, 0u, 0u, 0u};
#pragma unroll
    for (int i = 0; i < 3; i++) {
        int idx = tid + i * 256;               // < 768 = 128 rows * 6 slots
        int row = idx / 6, slot = idx % 6;
        *(uint4*)(g_xah + (size_t)(m0 + row) * BKH + 16 + slot * 8) = z;
    }
#undef XPF
}

// ---------------------------------------------------------------------------
// 3) GEMM (R12 config, best measured): out = sum_{65 chunks} A.B + bias
//    128x128 tiles, 8 warps of 64x32 (2x4 grid), 2 CTAs/SM, 3-stage
//    pipeline, ldmatrix.x4 loads, per-warp kk rotation. Prefetch split:
//    A-half at j==0, B-half + commit at j==1 (one group per chunk).
// ---------------------------------------------------------------------------
__global__ void __launch_bounds__(GTHREADS, 2)
gemm_kernel(const float* __restrict__ bias, float* __restrict__ out) {
    extern __shared__ char smem[];
    float* smf = (float*)smem;
    const int tid  = threadIdx.x;
    const int lane = tid & 31;
    const int wid  = tid >> 5;
    const int gid  = lane >> 2;      // 0..7
    const int tig  = lane & 3;       // 0..3
    const int wm   = wid & 1;        // warp M (2)
    const int wn   = wid >> 1;       // warp N (4)

    const int n0 = blockIdx.x * BN;
    const int m0 = blockIdx.y * BM;
    const int sel = g_sel[m0 >> 11];

    if (tid < BN) smf[tid] = bias[n0 + tid];

    const uint32_t sbase = smem_u32(smem);
    const int rowA = tid >> 3;       // 0..31 (+32*i)
    const int q    = tid & 7;        // 16B slot within 128B row
    const __half* srcA  = g_xh + (size_t)(m0 + rowA) * DIN + q * 8;
    const __half* srcB  = g_wh + (size_t)(n0 + rowA) * DIN + q * 8;
    const __half* srcAe = g_xah  + (size_t)(m0 + rowA) * BKH + q * 8;
    const __half* srcBe = g_bwhx + ((size_t)sel * DOUT + (n0 + rowA)) * BKH + q * 8;
    const uint32_t dstA = sbase + OFF_A + (uint32_t)(rowA * ROWB + q * 16);
    const uint32_t dstB = sbase + OFF_B + (uint32_t)(rowA * ROWB + q * 16);

    // per-lane ldmatrix base offsets (R9-proven maps)
    const uint32_t aoffl = (uint32_t)((wm * 64 + (lane & 15)) * ROWB
                                      + ((lane >> 4) & 1) * 16);
    const uint32_t boffl = (uint32_t)((wn * 32 + ((lane >> 4) & 1) * 8
                                       + (lane & 7)) * ROWB
                                      + ((lane >> 3) & 1) * 16);

#define PREFETCH_A(cn, st) do {                                               \
    if ((cn) < NCH) {                                                         \
        const __half* _a = srcA + (size_t)(cn) * BKH;                         \
        _Pragma("unroll")                                                     \
        for (int i = 0; i < 4; i++)                                           \
            cp_async16(dstA + (st) * A_STGB + i * (32 * ROWB),                \
                       _a + (size_t)(32 * i) * DIN);                          \
    } else {                                                                  \
        _Pragma("unroll")                                                     \
        for (int i = 0; i < 4; i++)                                           \
            cp_async16(dstA + (st) * A_STGB + i * (32 * ROWB),                \
                       srcAe + (size_t)(32 * i) * BKH);                       \
    }                                                                         \
} while (0)

#define PREFETCH_B(cn, st) do {                                               \
    if ((cn) < NCH) {                                                         \
        const __half* _b = srcB + (size_t)(cn) * BKH;                         \
        _Pragma("unroll")                                                     \
        for (int i = 0; i < 4; i++)                                           \
            cp_async16(dstB + (st) * B_STGB + i * (32 * ROWB),                \
                       _b + (size_t)(32 * i) * DIN);                          \
    } else {                                                                  \
        _Pragma("unroll")                                                     \
        for (int i = 0; i < 4; i++)                                           \
            cp_async16(dstB + (st) * B_STGB + i * (32 * ROWB),                \
                       srcBe + (size_t)(32 * i) * BKH);                       \
    }                                                                         \
} while (0)

    PREFETCH_A(0, 0); PREFETCH_B(0, 0); CP_COMMIT();
    PREFETCH_A(1, 1); PREFETCH_B(1, 1); CP_COMMIT();

    // per-warp kk rotation: all 4 phases present on each SMSP (wid 0..7)
    const uint32_t kbase = (uint32_t)(wid & 3) * 32u;

    float d[4][4][4];
#pragma unroll
    for (int mt = 0; mt < 4; mt++)
#pragma unroll
        for (int nt = 0; nt < 4; nt++)
#pragma unroll
            for (int r = 0; r < 4; r++) d[mt][nt][r] = 0.0f;

    for (int c = 0; c < NCHT; c++) {
        const int st = c % 3;
        CP_WAIT1();                   // chunk c's group complete
        __syncthreads();              // all warps done with stage (c-1)%3

        const uint32_t As = sbase + OFF_A + st * A_STGB + aoffl;
        const uint32_t Bs = sbase + OFF_B + st * B_STGB + boffl;

        int cn = c + 2; if (cn > NCH) cn = NCH;   // clamped duplicate tail
        const int stp = (c + 2) % 3;

#pragma unroll
        for (int j = 0; j < 4; j++) {
            // rotated kk: warp processes sub-chunks in order (wid&3), +1, ...
            const uint32_t koff = (kbase + (uint32_t)j * 32u) & 127u;
            uint32_t a[4][4];
#pragma unroll
            for (int mt = 0; mt < 4; mt++)
                ldsm4(a[mt][0], a[mt][1], a[mt][2], a[mt][3],
                      As + mt * (16 * ROWB) + koff);
            uint32_t b[4][2];
#pragma unroll
            for (int p = 0; p < 2; p++)
                ldsm4(b[2 * p][0], b[2 * p][1], b[2 * p + 1][0], b[2 * p + 1][1],
                      Bs + p * (16 * ROWB) + koff);
#pragma unroll
            for (int mt = 0; mt < 4; mt++)
#pragma unroll
                for (int nt = 0; nt < 4; nt++)
                    mma_f16(d[mt][nt], a[mt][0], a[mt][1], a[mt][2], a[mt][3],
                            b[nt][0], b[nt][1]);

            // prefetch split across j blocks to smooth the LSU burst;
            // exactly ONE commit per chunk -> wait accounting unchanged.
            if (j == 0) { PREFETCH_A(cn, stp); }
            if (j == 1) { PREFETCH_B(cn, stp); CP_COMMIT(); }
        }
    }
    CP_WAIT0();

    // ---- epilogue: fused bias ----
    const float* bs = smf + wn * 32;
#pragma unroll
    for (int mt = 0; mt < 4; mt++) {
        const int r = m0 + wm * 64 + mt * 16 + gid;
        float* o0p = out + (size_t)r * DOUT + n0 + wn * 32;
        float* o1p = o0p + (size_t)8 * DOUT;
#pragma unroll
        for (int nt = 0; nt < 4; nt++) {
            const int col = nt * 8 + tig * 2;
            float2 v0, v1;
            v0.x = d[mt][nt][0] + bs[col];
            v0.y = d[mt][nt][1] + bs[col + 1];
            v1.x = d[mt][nt][2] + bs[col];
            v1.y = d[mt][nt][3] + bs[col + 1];
            *(float2*)(o0p + col) = v0;
            *(float2*)(o1p + col) = v1;
        }
    }
#undef PREFETCH_A
#undef PREFETCH_B
}

// ---------------------------------------------------------------------------
// launch
// ---------------------------------------------------------------------------
extern "C" void kernel_launch(void* const* d_in, const int* in_sizes, int n_in,
                              void* d_out, int out_size) {
    const float* x      = (const float*)d_in[0];
    const float* weight = (const float*)d_in[1];
    const float* bias   = (const float*)d_in[2];
    const float* lora_A = (const float*)d_in[3];
    const float* lora_B = (const float*)d_in[4];
    const void*  starts = d_in[5];
    float* out = (float*)d_out;
    const int n_starts = in_sizes[5];

    cvt_kernel<<<CVT_BLOCKS, 256>>>(weight, x, lora_A, lora_B, starts, n_starts);
    xag_kernel<<<MROWS / 128, 256>>>();

    cudaFuncSetAttribute(gemm_kernel,
                         cudaFuncAttributeMaxDynamicSharedMemorySize, SMEM_BYTES);
    dim3 grid(DOUT / BN, MROWS / BM);  // (32, 128)
    gemm_kernel<<<grid, GTHREADS, SMEM_BYTES>>>(bias, out);
}

// round 15
// speedup vs baseline: 1.1375x; 1.0749x over previous
#include <cuda_runtime.h>
#include <cuda_fp16.h>
#include <cstdint>

// ============================================================================
// MultiLoraLinear — fp16 HMMA path, v12 (4-way prefetch burst smoothing)
//   out = x @ W^T + bias + LoRA(per-segment, rank 16)
//
// CRITICAL RULE: NEVER pass a __device__ global as a kernel argument from
// host code (host-side shadow address; on GB300/ATS it silently writes host
// memory). All scratch globals are referenced from device code only.
//
// v12: R14 state (best measured: 1378 us) with the chunk prefetch split
// 4 ways across the j blocks (A/2 @ j0, A/2 @ j1, B/2 @ j2, B/2 @ j3 +
// commit). Burst smoothing is the one mechanism that measurably helped the
// GEMM beyond occupancy (R14: 2-way split -45 us). One commit per chunk —
// cp.async group accounting unchanged; 3-stage buffer gives the late commit
// a full chunk of slack before its consumer's wait_group 1.
//
//   1) cvt_kernel : g_wh = half(W), g_xh = half(x), + sel/lahx/bwhx tables
//   2) xag_kernel : HMMA mini GEMM  g_xah = [x @ A_sel^T * scale | 0]
//   3) gemm_kernel: main GEMM, K = 65 chunks of 64 halves (last = LoRA ext)
// ============================================================================

#define DIN      4096
#define DOUT     4096
#define NBATCH   8
#define MROWS    16384
#define RANK     16
#define NLORA    3
#define SCALE_F  1.0f                // alpha / rank

#define BM       128
#define BN       128
#define BKH      64                  // K halves per chunk (= 128 B per row)
#define NCH      (DIN / BKH)         // 64 main chunks
#define NCHT     (NCH + 1)           // +1 LoRA extension chunk
#define GTHREADS 256

// GEMM SMEM (bytes): bias 128 floats | 3x A stage | 3x B stage
#define ROWB     144                 // padded row stride bytes (72 halves)
#define OFF_A    1024
#define A_STGB   (BM * ROWB)         // 18432
#define OFF_B    (OFF_A + 3 * A_STGB)
#define B_STGB   (BN * ROWB)         // 18432
#define SMEM_BYTES (OFF_B + 3 * B_STGB)   // 111616  -> 2 CTAs/SM

// merged convert+prep kernel block ranges
#define WH_BLOCKS   8192             // DOUT*DIN/8/256
#define XH_BLOCKS   32768            // MROWS*DIN/8/256
#define BWHX_BLOCKS 4096             // (NLORA+1)*DOUT*64 / 256
#define LAH_BLOCKS  1024             // (NLORA+1)*RANK*DIN / 256
#define CVT_BLOCKS  (WH_BLOCKS + XH_BLOCKS + BWHX_BLOCKS + LAH_BLOCKS + 1)

// ---------------------------------------------------------------------------
// device scratch (no cudaMalloc allowed; referenced ONLY from device code)
// ---------------------------------------------------------------------------
__device__ __half g_wh[(size_t)DOUT * DIN];                  // 32 MB
__device__ __half g_xh[(size_t)MROWS * DIN];                 // 128 MB
__device__ __half g_xah[(size_t)MROWS * BKH];                // 2 MB [xa|0]
__device__ __half g_bwhx[(size_t)(NLORA + 1) * DOUT * BKH];  // 2 MB
__device__ __half g_lahx[(size_t)(NLORA + 1) * RANK * DIN];  // 512 KB
__device__ int    g_sel[NBATCH];

// ---------------------------------------------------------------------------
// helpers
// ---------------------------------------------------------------------------
__device__ __forceinline__ uint32_t smem_u32(const void* p) {
    uint32_t a;
    asm("{ .reg .u64 t; cvta.to.shared.u64 t, %1; cvt.u32.u64 %0, t; }"
        : "=r"(a) : "l"(p));
    return a;
}

__device__ __forceinline__ void cp_async16(uint32_t dst_smem, const void* src) {
    asm volatile("cp.async.cg.shared.global [%0], [%1], 16;"
                 :: "r"(dst_smem), "l"(src) : "memory");
}
#define CP_COMMIT() asm volatile("cp.async.commit_group;" ::: "memory")
#define CP_WAIT1()  asm volatile("cp.async.wait_group 1;" ::: "memory")
#define CP_WAIT0()  asm volatile("cp.async.wait_group 0;" ::: "memory")

__device__ __forceinline__ void mma_f16(float* d, uint32_t a0, uint32_t a1,
                                        uint32_t a2, uint32_t a3,
                                        uint32_t b0, uint32_t b1) {
    asm volatile(
        "mma.sync.aligned.m16n8k16.row.col.f32.f16.f16.f32 "
        "{%0,%1,%2,%3}, {%4,%5,%6,%7}, {%8,%9}, {%0,%1,%2,%3};"
        : "+f"(d[0]), "+f"(d[1]), "+f"(d[2]), "+f"(d[3])
        : "r"(a0), "r"(a1), "r"(a2), "r"(a3), "r"(b0), "r"(b1));
}

__device__ __forceinline__ void ldsm4(uint32_t& r0, uint32_t& r1,
                                      uint32_t& r2, uint32_t& r3,
                                      uint32_t addr) {
    asm volatile("ldmatrix.sync.aligned.m8n8.x4.shared.b16 {%0,%1,%2,%3}, [%4];"
                 : "=r"(r0), "=r"(r1), "=r"(r2), "=r"(r3) : "r"(addr));
}

__device__ __forceinline__ void cvt8(const float4* s4, __half* dst, size_t idx) {
    float4 a = s4[2 * idx], b = s4[2 * idx + 1];
    __half2 h[4];
    h[0] = __floats2half2_rn(a.x, a.y);
    h[1] = __floats2half2_rn(a.z, a.w);
    h[2] = __floats2half2_rn(b.x, b.y);
    h[3] = __floats2half2_rn(b.z, b.w);
    *(uint4*)(dst + idx * 8) = *(const uint4*)h;
}

// ---------------------------------------------------------------------------
// 1) cvt+prep merged: W->half, x->half, lora tables, sel — by blockIdx range
// ---------------------------------------------------------------------------
__global__ void __launch_bounds__(256) cvt_kernel(
    const float* __restrict__ W, const float* __restrict__ x,
    const float* __restrict__ lA, const float* __restrict__ lB,
    const void* __restrict__ starts_raw, int n_starts) {
    const int bid = blockIdx.x;
    const int tid = threadIdx.x;

    if (bid < WH_BLOCKS) {
        size_t idx = (size_t)bid * 256 + tid;
        cvt8((const float4*)W, g_wh, idx);
    } else if (bid < WH_BLOCKS + XH_BLOCKS) {
        size_t idx = (size_t)(bid - WH_BLOCKS) * 256 + tid;
        cvt8((const float4*)x, g_xh, idx);
    } else if (bid < WH_BLOCKS + XH_BLOCKS + BWHX_BLOCKS) {
        // g_bwhx[a][n][c] = (a>0 && c<16) ? half(lora_B[a-1][n][c]) : 0
        int idx = (bid - WH_BLOCKS - XH_BLOCKS) * 256 + tid;
        int c = idx & 63;
        int n = (idx >> 6) & (DOUT - 1);
        int a = idx >> 18;
        float v = 0.0f;
        if (a > 0 && c < RANK)
            v = lB[((size_t)(a - 1) * DOUT + n) * RANK + c];
        g_bwhx[idx] = __float2half_rn(v);
    } else if (bid < WH_BLOCKS + XH_BLOCKS + BWHX_BLOCKS + LAH_BLOCKS) {
        // g_lahx: [0 | lora_A] fp16, slab 0 = zeros
        int idx = (bid - WH_BLOCKS - XH_BLOCKS - BWHX_BLOCKS) * 256 + tid;
        int a = idx >> 16;                       // / (RANK*DIN)
        float v = 0.0f;
        if (a > 0) v = lA[(size_t)idx - (size_t)RANK * DIN];
        g_lahx[idx] = __float2half_rn(v);
    } else if (tid < 32) {
        // sel: searchsorted(starts, b, 'right') - 1; dtype-robust (i32/i64)
        const long long* s64 = (const long long*)starts_raw;
        const int*       s32 = (const int*)starts_raw;
        bool ok64 = true;
        long long prev = -1;
        for (int j = 0; j < n_starts; j++) {
            long long v = s64[j];
            if (v < 0 || v >= 64 || v < prev) { ok64 = false; break; }
            prev = v;
        }
        int b = tid;
        if (b < NBATCH) {
            int cnt = 0;
            for (int j = 0; j < n_starts; j++) {
                long long v = ok64 ? s64[j] : (long long)s32[j];
                cnt += (v <= (long long)b);
            }
            int seg = cnt - 1;
            int id = 0;
            if (seg > 0) { id = seg; if (id > NLORA) id = NLORA; }
            g_sel[b] = id;
        }
    }
}

// ---------------------------------------------------------------------------
// 2) xag: g_xah[m][0:16] = scale * (g_xh[m] @ A_sel^T);  cols 16..63 = 0
//    128 rows / CTA, 8 warps (16 rows each), HMMA m16n8k16,
//    LDS.32 fragment loads, 2-stage cp.async.  (proven)
// ---------------------------------------------------------------------------
#define XR 144                       // padded row bytes
#define XS_STG (128 * XR)            // 18432
#define AS_STG (16 * XR)             // 2304

__global__ void __launch_bounds__(256) xag_kernel() {
    __shared__ char sm2[2 * XS_STG + 2 * AS_STG];   // 41472 B static
    const int tid  = threadIdx.x;
    const int lane = tid & 31;
    const int wid  = tid >> 5;
    const int gid  = lane >> 2;      // 0..7
    const int tig  = lane & 3;       // 0..3
    const int m0   = blockIdx.x * 128;
    const int sel  = g_sel[m0 >> 11];

    const int rowA = tid >> 3;       // 0..31 (+32*i)
    const int q    = tid & 7;
    const uint32_t sbase = smem_u32(sm2);
    const __half* srcX = g_xh + (size_t)(m0 + rowA) * DIN + q * 8;
    const __half* srcL = g_lahx + (size_t)sel * RANK * DIN
                       + (size_t)(tid >> 3) * DIN + q * 8;
    const uint32_t dstX = sbase + (uint32_t)(rowA * XR + q * 16);
    const uint32_t dstL = sbase + 2 * XS_STG + (uint32_t)((tid >> 3) * XR + q * 16);

#define XPF(cn, st) do {                                                      \
    const __half* _x = srcX + (size_t)(cn) * BKH;                             \
    _Pragma("unroll")                                                         \
    for (int i = 0; i < 4; i++)                                               \
        cp_async16(dstX + (st) * XS_STG + i * (32 * XR),                      \
                   _x + (size_t)(32 * i) * DIN);                              \
    if (tid < 128)                                                            \
        cp_async16(dstL + (st) * AS_STG, srcL + (size_t)(cn) * BKH);          \
} while (0)

    XPF(0, 0); CP_COMMIT();

    float d[2][4];
#pragma unroll
    for (int nt = 0; nt < 2; nt++)
#pragma unroll
        for (int r = 0; r < 4; r++) d[nt][r] = 0.0f;

    for (int c = 0; c < NCH; c++) {
        const int st = c & 1;
        CP_WAIT0();
        __syncthreads();
        if (c + 1 < NCH) { XPF(c + 1, st ^ 1); CP_COMMIT(); }

        const char* Xs = sm2 + st * XS_STG;
        const char* As = sm2 + 2 * XS_STG + st * AS_STG;
#pragma unroll
        for (int kk = 0; kk < 4; kk++) {
            const int koff = kk * 32;           // bytes (16 halves)
            const int r = wid * 16 + gid;
            const char* p0 = Xs + r * XR + koff + tig * 4;
            const char* p1 = Xs + (r + 8) * XR + koff + tig * 4;
            uint32_t a0 = *(const uint32_t*)(p0);
            uint32_t a1 = *(const uint32_t*)(p1);
            uint32_t a2 = *(const uint32_t*)(p0 + 16);
            uint32_t a3 = *(const uint32_t*)(p1 + 16);
            uint32_t b[2][2];
#pragma unroll
            for (int nt = 0; nt < 2; nt++) {
                const char* p = As + (nt * 8 + gid) * XR + koff + tig * 4;
                b[nt][0] = *(const uint32_t*)(p);
                b[nt][1] = *(const uint32_t*)(p + 16);
            }
            mma_f16(d[0], a0, a1, a2, a3, b[0][0], b[0][1]);
            mma_f16(d[1], a0, a1, a2, a3, b[1][0], b[1][1]);
        }
        __syncthreads();              // stage reuse guard before next overwrite
    }

    // epilogue: cols 0..15 from accumulators (std mma d layout), 16..63 zero
#pragma unroll
    for (int nt = 0; nt < 2; nt++) {
        const int col = nt * 8 + tig * 2;
        const int r0 = m0 + wid * 16 + gid;
        __half2 v0 = __floats2half2_rn(d[nt][0] * SCALE_F, d[nt][1] * SCALE_F);
        __half2 v1 = __floats2half2_rn(d[nt][2] * SCALE_F, d[nt][3] * SCALE_F);
        *(__half2*)(g_xah + (size_t)r0 * BKH + col) = v0;
        *(__half2*)(g_xah + (size_t)(r0 + 8) * BKH + col) = v1;
    }
    const uint4 z = {0u, 0u, 0u, 0u};
#pragma unroll
    for (int i = 0; i < 3; i++) {
        int idx = tid + i * 256;               // < 768 = 128 rows * 6 slots
        int row = idx / 6, slot = idx % 6;
        *(uint4*)(g_xah + (size_t)(m0 + row) * BKH + 16 + slot * 8) = z;
    }
#undef XPF
}

// ---------------------------------------------------------------------------
// 3) GEMM: out = sum_{65 chunks} A.B + bias
//    128x128 tiles, 8 warps of 64x32 (2x4 grid), 2 CTAs/SM, 3-stage
//    pipeline, ldmatrix.x4 loads, per-warp kk rotation. Prefetch split
//    4 ways across j blocks (A/2, A/2, B/2, B/2+commit).
// ---------------------------------------------------------------------------
__global__ void __launch_bounds__(GTHREADS, 2)
gemm_kernel(const float* __restrict__ bias, float* __restrict__ out) {
    extern __shared__ char smem[];
    float* smf = (float*)smem;
    const int tid  = threadIdx.x;
    const int lane = tid & 31;
    const int wid  = tid >> 5;
    const int gid  = lane >> 2;      // 0..7
    const int tig  = lane & 3;       // 0..3
    const int wm   = wid & 1;        // warp M (2)
    const int wn   = wid >> 1;       // warp N (4)

    const int n0 = blockIdx.x * BN;
    const int m0 = blockIdx.y * BM;
    const int sel = g_sel[m0 >> 11];

    if (tid < BN) smf[tid] = bias[n0 + tid];

    const uint32_t sbase = smem_u32(smem);
    const int rowA = tid >> 3;       // 0..31 (+32*i)
    const int q    = tid & 7;        // 16B slot within 128B row
    const __half* srcA  = g_xh + (size_t)(m0 + rowA) * DIN + q * 8;
    const __half* srcB  = g_wh + (size_t)(n0 + rowA) * DIN + q * 8;
    const __half* srcAe = g_xah  + (size_t)(m0 + rowA) * BKH + q * 8;
    const __half* srcBe = g_bwhx + ((size_t)sel * DOUT + (n0 + rowA)) * BKH + q * 8;
    const uint32_t dstA = sbase + OFF_A + (uint32_t)(rowA * ROWB + q * 16);
    const uint32_t dstB = sbase + OFF_B + (uint32_t)(rowA * ROWB + q * 16);

    // per-lane ldmatrix base offsets (R9-proven maps)
    const uint32_t aoffl = (uint32_t)((wm * 64 + (lane & 15)) * ROWB
                                      + ((lane >> 4) & 1) * 16);
    const uint32_t boffl = (uint32_t)((wn * 32 + ((lane >> 4) & 1) * 8
                                       + (lane & 7)) * ROWB
                                      + ((lane >> 3) & 1) * 16);

// quarter prefetch: h = 0/1 selects row half (rows 0-63 / 64-127), 2 cp.async
#define PF_A(cn, st, h) do {                                                  \
    if ((cn) < NCH) {                                                         \
        const __half* _a = srcA + (size_t)(cn) * BKH;                         \
        _Pragma("unroll")                                                     \
        for (int i = 2*(h); i < 2*(h)+2; i++)                                 \
            cp_async16(dstA + (st) * A_STGB + i * (32 * ROWB),                \
                       _a + (size_t)(32 * i) * DIN);                          \
    } else {                                                                  \
        _Pragma("unroll")                                                     \
        for (int i = 2*(h); i < 2*(h)+2; i++)                                 \
            cp_async16(dstA + (st) * A_STGB + i * (32 * ROWB),                \
                       srcAe + (size_t)(32 * i) * BKH);                       \
    }                                                                         \
} while (0)

#define PF_B(cn, st, h) do {                                                  \
    if ((cn) < NCH) {                                                         \
        const __half* _b = srcB + (size_t)(cn) * BKH;                         \
        _Pragma("unroll")                                                     \
        for (int i = 2*(h); i < 2*(h)+2; i++)                                 \
            cp_async16(dstB + (st) * B_STGB + i * (32 * ROWB),                \
                       _b + (size_t)(32 * i) * DIN);                          \
    } else {                                                                  \
        _Pragma("unroll")                                                     \
        for (int i = 2*(h); i < 2*(h)+2; i++)                                 \
            cp_async16(dstB + (st) * B_STGB + i * (32 * ROWB),                \
                       srcBe + (size_t)(32 * i) * BKH);                       \
    }                                                                         \
} while (0)

    PF_A(0, 0, 0); PF_A(0, 0, 1); PF_B(0, 0, 0); PF_B(0, 0, 1); CP_COMMIT();
    PF_A(1, 1, 0); PF_A(1, 1, 1); PF_B(1, 1, 0); PF_B(1, 1, 1); CP_COMMIT();

    // per-warp kk rotation: all 4 phases present on each SMSP (wid 0..7)
    const uint32_t kbase = (uint32_t)(wid & 3) * 32u;

    float d[4][4][4];
#pragma unroll
    for (int mt = 0; mt < 4; mt++)
#pragma unroll
        for (int nt = 0; nt < 4; nt++)
#pragma unroll
            for (int r = 0; r < 4; r++) d[mt][nt][r] = 0.0f;

    for (int c = 0; c < NCHT; c++) {
        const int st = c % 3;
        CP_WAIT1();                   // chunk c's group complete
        __syncthreads();              // all warps done with stage (c-1)%3

        const uint32_t As = sbase + OFF_A + st * A_STGB + aoffl;
        const uint32_t Bs = sbase + OFF_B + st * B_STGB + boffl;

        int cn = c + 2; if (cn > NCH) cn = NCH;   // clamped duplicate tail
        const int stp = (c + 2) % 3;

#pragma unroll
        for (int j = 0; j < 4; j++) {
            // rotated kk: warp processes sub-chunks in order (wid&3), +1, ...
            const uint32_t koff = (kbase + (uint32_t)j * 32u) & 127u;
            uint32_t a[4][4];
#pragma unroll
            for (int mt = 0; mt < 4; mt++)
                ldsm4(a[mt][0], a[mt][1], a[mt][2], a[mt][3],
                      As + mt * (16 * ROWB) + koff);
            uint32_t b[4][2];
#pragma unroll
            for (int p = 0; p < 2; p++)
                ldsm4(b[2 * p][0], b[2 * p][1], b[2 * p + 1][0], b[2 * p + 1][1],
                      Bs + p * (16 * ROWB) + koff);
#pragma unroll
            for (int mt = 0; mt < 4; mt++)
#pragma unroll
                for (int nt = 0; nt < 4; nt++)
                    mma_f16(d[mt][nt], a[mt][0], a[mt][1], a[mt][2], a[mt][3],
                            b[nt][0], b[nt][1]);

            // 4-way split prefetch: one quarter per j block, ONE commit/chunk
            if (j == 0)      { PF_A(cn, stp, 0); }
            else if (j == 1) { PF_A(cn, stp, 1); }
            else if (j == 2) { PF_B(cn, stp, 0); }
            else             { PF_B(cn, stp, 1); CP_COMMIT(); }
        }
    }
    CP_WAIT0();

    // ---- epilogue: fused bias ----
    const float* bs = smf + wn * 32;
#pragma unroll
    for (int mt = 0; mt < 4; mt++) {
        const int r = m0 + wm * 64 + mt * 16 + gid;
        float* o0p = out + (size_t)r * DOUT + n0 + wn * 32;
        float* o1p = o0p + (size_t)8 * DOUT;
#pragma unroll
        for (int nt = 0; nt < 4; nt++) {
            const int col = nt * 8 + tig * 2;
            float2 v0, v1;
            v0.x = d[mt][nt][0] + bs[col];
            v0.y = d[mt][nt][1] + bs[col + 1];
            v1.x = d[mt][nt][2] + bs[col];
            v1.y = d[mt][nt][3] + bs[col + 1];
            *(float2*)(o0p + col) = v0;
            *(float2*)(o1p + col) = v1;
        }
    }
#undef PF_A
#undef PF_B
}

// ---------------------------------------------------------------------------
// launch
// ---------------------------------------------------------------------------
extern "C" void kernel_launch(void* const* d_in, const int* in_sizes, int n_in,
                              void* d_out, int out_size) {
    const float* x      = (const float*)d_in[0];
    const float* weight = (const float*)d_in[1];
    const float* bias   = (const float*)d_in[2];
    const float* lora_A = (const float*)d_in[3];
    const float* lora_B = (const float*)d_in[4];
    const void*  starts = d_in[5];
    float* out = (float*)d_out;
    const int n_starts = in_sizes[5];

    cvt_kernel<<<CVT_BLOCKS, 256>>>(weight, x, lora_A, lora_B, starts, n_starts);
    xag_kernel<<<MROWS / 128, 256>>>();

    cudaFuncSetAttribute(gemm_kernel,
                         cudaFuncAttributeMaxDynamicSharedMemorySize, SMEM_BYTES);
    dim3 grid(DOUT / BN, MROWS / BM);  // (32, 128)
    gemm_kernel<<<grid, GTHREADS, SMEM_BYTES>>>(bias, out);
}